// round 4
// baseline (speedup 1.0000x reference)
#include <cuda_runtime.h>
#include <stdint.h>

// ---------------- constants ----------------
#define EPSc   0.05f
#define DTc    0.1f
#define RMINc  1.0e5f
#define RMAXc  1.0e7f
#define CMINc  1.0e-7f
#define CMAXc  1.0e-4f

// ---------------- device scratch (static: no allocation allowed) ----------------
__device__ float g_thn1T[4*32*34];        // [n][o][m]
__device__ float g_thn2T[4*32*1058];      // [n][o][m]
__device__ float g_w1s  [4*33*32];        // [n][m][o]  (thn/denom, m=32 is bias)
__device__ float g_w2s  [4*1057*32];      // [n][m][o]  (m=1056 is bias)
__device__ float g_a1   [4*32*32*256];    // [n][b][c][t]
__device__ float g_a1T  [4*32*256*32];    // [n][c][t][b]
__device__ float g_beta [2*256*1024*4];   // [bank][t][k][n]
__device__ float g_s0   [2*1024*4*32];    // [bank][k][n][b]
__device__ float g_yout [4*1024*256*32];  // [n][k][t][b]   (128 MB)

// ---------------- JAX threefry2x32 (partitionable semantics) ----------------
__device__ __forceinline__ uint2 tf2x32_d(uint32_t k0, uint32_t k1, uint32_t c0, uint32_t c1) {
    uint32_t ks2 = k0 ^ k1 ^ 0x1BD11BDAu;
    uint32_t x0 = c0 + k0, x1 = c1 + k1;
#define TFR(r) { x0 += x1; x1 = __funnelshift_l(x1, x1, (r)); x1 ^= x0; }
    TFR(13) TFR(15) TFR(26) TFR(6)   x0 += k1;  x1 += ks2 + 1u;
    TFR(17) TFR(29) TFR(16) TFR(24)  x0 += ks2; x1 += k0  + 2u;
    TFR(13) TFR(15) TFR(26) TFR(6)   x0 += k0;  x1 += k1  + 3u;
    TFR(17) TFR(29) TFR(16) TFR(24)  x0 += k1;  x1 += ks2 + 4u;
    TFR(13) TFR(15) TFR(26) TFR(6)   x0 += ks2; x1 += k0  + 5u;
#undef TFR
    return make_uint2(x0, x1);
}

// uniform [0,1) for flat element idx, partitionable random_bits = fold(out0^out1)
__device__ __forceinline__ float u01p(uint2 key, uint32_t idx) {
    uint2 v = tf2x32_d(key.x, key.y, 0u, idx);
    uint32_t u = v.x ^ v.y;
    return __uint_as_float((u >> 9) | 0x3f800000u) - 1.0f;
}

// ---------------- kernel: noisy effective theta (pmac1) ----------------
__global__ void k_thn1(uint2 key, const float* __restrict__ th) {
    int i = blockIdx.x * blockDim.x + threadIdx.x;
    if (i >= 4*34*32) return;
    int o = i & 31; int nm = i >> 5; int m = nm % 34; int n = nm / 34;
    float u = u01p(key, (uint32_t)i);
    float noise = (u * 2.0f - 1.0f) * EPSc + 1.0f;
    float t = th[m*32 + o];
    t = fminf(fmaxf(t, -10.0f), 10.0f);
    if (fabsf(t) < 0.01f) t = 0.0f;
    g_thn1T[(n*32 + o)*34 + m] = t * noise;
}

// ---------------- kernel: noisy effective theta (pmac2) ----------------
__global__ void k_thn2(uint2 key, const float* __restrict__ th) {
    int i = blockIdx.x * blockDim.x + threadIdx.x;
    if (i >= 4*1058*32) return;
    int o = i & 31; int nm = i >> 5; int m = nm % 1058; int n = nm / 1058;
    float u = u01p(key, (uint32_t)i);
    float noise = (u * 2.0f - 1.0f) * EPSc + 1.0f;
    float t = th[m*32 + o];
    t = fminf(fmaxf(t, -10.0f), 10.0f);
    if (fabsf(t) < 0.01f) t = 0.0f;
    g_thn2T[(n*32 + o)*1058 + m] = t * noise;
}

// ---------------- kernel: normalize columns (one warp per (n,o)) ----------------
__global__ void k_norm() {
    int gid = blockIdx.x * blockDim.x + threadIdx.x;
    int w = gid >> 5, lane = gid & 31;
    if (w < 128) {          // pmac2 columns
        int n = w >> 5, o = w & 31;
        const float* col = &g_thn2T[(n*32 + o)*1058];
        float s = 0.0f;
        for (int m = lane; m < 1058; m += 32) s += fabsf(col[m]);
        #pragma unroll
        for (int d = 16; d > 0; d >>= 1) s += __shfl_xor_sync(0xffffffffu, s, d);
        float inv = 1.0f / (s + 1e-10f);
        for (int m = lane; m < 1057; m += 32) g_w2s[(n*1057 + m)*32 + o] = col[m] * inv;
    } else if (w < 256) {   // pmac1 columns
        int w2 = w - 128; int n = w2 >> 5, o = w2 & 31;
        const float* col = &g_thn1T[(n*32 + o)*34];
        float s = 0.0f;
        for (int m = lane; m < 34; m += 32) s += fabsf(col[m]);
        #pragma unroll
        for (int d = 16; d > 0; d >>= 1) s += __shfl_xor_sync(0xffffffffu, s, d);
        float inv = 1.0f / (s + 1e-10f);
        for (int m = lane; m < 33; m += 32) g_w1s[(n*33 + m)*32 + o] = col[m] * inv;
    }
}

// ---------------- kernel: pmac1 (x -> a1, both layouts) ----------------
__global__ void __launch_bounds__(256) k_pmac1(const float* __restrict__ x) {
    int n = blockIdx.x >> 5, b = blockIdx.x & 31, t = threadIdx.x;
    __shared__ float w[33*32];
    for (int i = threadIdx.x; i < 33*32; i += 256) w[i] = g_w1s[n*33*32 + i];
    __syncthreads();
    const float* xp = x + ((n*32 + b)*32) * 256 + t;   // m stride 256
    float acc[32];
    const float4* wb = (const float4*)&w[32*32];
    #pragma unroll
    for (int o4 = 0; o4 < 8; o4++) {
        float4 v = wb[o4];
        acc[4*o4+0]=v.x; acc[4*o4+1]=v.y; acc[4*o4+2]=v.z; acc[4*o4+3]=v.w;
    }
    #pragma unroll 4
    for (int m = 0; m < 32; m++) {
        float xv = xp[m*256];
        const float4* wr = (const float4*)&w[m*32];
        #pragma unroll
        for (int o4 = 0; o4 < 8; o4++) {
            float4 v = wr[o4];
            acc[4*o4+0]=fmaf(xv,v.x,acc[4*o4+0]); acc[4*o4+1]=fmaf(xv,v.y,acc[4*o4+1]);
            acc[4*o4+2]=fmaf(xv,v.z,acc[4*o4+2]); acc[4*o4+3]=fmaf(xv,v.w,acc[4*o4+3]);
        }
    }
    #pragma unroll
    for (int o = 0; o < 32; o++) {
        float a = 0.05f + 0.5f * tanhf((acc[o] - 0.3f) * 3.0f);
        g_a1 [((n*32 + b)*32 + o)*256 + t] = a;
        g_a1T[((n*32 + o)*256 + t)*32 + b] = a;
    }
}

// ---------------- kernel: beta for both banks ----------------
__global__ void k_beta(uint2 kR1, uint2 kC1, uint2 km1,
                       uint2 kR2, uint2 kC2, uint2 km2,
                       const float* __restrict__ Rlf, const float* __restrict__ Clf) {
    int i = blockIdx.x * blockDim.x + threadIdx.x;
    if (i >= 2*1048576) return;
    int bank = i >> 20;
    uint32_t e = (uint32_t)(i & 1048575);
    int k = (int)((e >> 2) & 1023u);
    uint2 kR = bank ? kR2 : kR1;
    uint2 kC = bank ? kC2 : kC1;
    uint2 km = bank ? km2 : km1;
    float nR = (u01p(kR, e) * 2.0f - 1.0f) * EPSc + 1.0f;
    float nC = (u01p(kC, e) * 2.0f - 1.0f) * EPSc + 1.0f;
    float mu =  u01p(km, e) * 0.2f + 1.0f;
    float Rr = Rlf[k*2 + bank], Cr = Clf[k*2 + bank];
    float Rt = (1.0f / (1.0f + expf(-Rr))) * (RMAXc - RMINc) + RMINc;
    float Ct = (1.0f / (1.0f + expf(-Cr))) * (CMAXc - CMINc) + CMINc;
    float RC = mu * (Rt * nR) * (Ct * nC);
    g_beta[i] = RC / (RC + DTc);
}

// ---------------- kernel: s0 for both banks ----------------
__global__ void k_s0(uint2 k01, uint2 k02) {
    int i = blockIdx.x * blockDim.x + threadIdx.x;
    if (i >= 262144) return;
    int bank = i >> 17;
    uint32_t e = (uint32_t)(i & 131071);
    g_s0[i] = u01p(bank ? k02 : k01, e);
}

// ---------------- kernel: fused two-bank scan ----------------
__global__ void __launch_bounds__(1024) k_scan() {
    int n = blockIdx.x & 3, c = blockIdx.x >> 2;
    int f = threadIdx.x >> 5, b = threadIdx.x & 31;
    int k = c*32 + f;
    float s = g_s0[(k*4 + n)*32 + b];
    float r = g_s0[131072 + (k*4 + n)*32 + b];
    const float* xp  = &g_a1T[((n*32 + c)*256) * 32 + b];   // +t*32
    const float* b1p = &g_beta[(k*4 + n)];                  // +t*4096
    const float* b2p = b1p + 1048576;
    float* yp = &g_yout[((n*1024 + k)*256) * 32 + b];       // +t*32
    #pragma unroll 4
    for (int t = 0; t < 256; t++) {
        float be1 = __ldg(b1p + t*4096);
        float be2 = __ldg(b2p + t*4096);
        float xv  = xp[t*32];
        yp[t*32] = r;                      // scan emits the PRE-update carry
        r = be2 * r + (1.0f - be2) * s;    // bank2 consumes y1[t] = current s
        s = be1 * s + (1.0f - be1) * xv;   // bank1 update
    }
}

// ---------------- kernel: pmac2 (h[1056] -> 32 outputs) ----------------
__global__ void __launch_bounds__(256) k_pmac2(float* __restrict__ out) {
    int n = blockIdx.y;
    int t = blockIdx.x * 8 + (threadIdx.x >> 5);
    int b = threadIdx.x & 31;
    __shared__ float wsm[264*32];   // 33.8 KB: one stage = 8 c-groups x 33 rows
    float acc[32];
    const float* wbias = &g_w2s[(n*1057 + 1056)*32];
    #pragma unroll
    for (int o = 0; o < 32; o++) acc[o] = wbias[o];
    const float* a1p = &g_a1T[((n*32)*256 + t)*32 + b];     // +c*8192
    const float* yop = &g_yout[((n*1024)*256 + t)*32 + b];  // +k*8192
    const float* wg  = &g_w2s[(n*1057)*32];
    for (int sIdx = 0; sIdx < 4; sIdx++) {
        __syncthreads();
        const float* src = wg + sIdx*264*32;
        for (int i = threadIdx.x; i < 264*32; i += 256) wsm[i] = src[i];
        __syncthreads();
        for (int cl = 0; cl < 8; cl++) {
            int c = sIdx*8 + cl;
            // g = 0 channel: raw a1
            {
                float h = a1p[c*8192];
                const float4* wr = (const float4*)&wsm[(cl*33)*32];
                #pragma unroll
                for (int o4 = 0; o4 < 8; o4++) {
                    float4 v = wr[o4];
                    acc[4*o4+0]=fmaf(h,v.x,acc[4*o4+0]); acc[4*o4+1]=fmaf(h,v.y,acc[4*o4+1]);
                    acc[4*o4+2]=fmaf(h,v.z,acc[4*o4+2]); acc[4*o4+3]=fmaf(h,v.w,acc[4*o4+3]);
                }
            }
            const float* yc = yop + c*32*8192;
            #pragma unroll 8
            for (int j = 0; j < 32; j++) {
                float hv = yc[j*8192];
                const float4* wr = (const float4*)&wsm[(cl*33 + 1 + j)*32];
                #pragma unroll
                for (int o4 = 0; o4 < 8; o4++) {
                    float4 v = wr[o4];
                    acc[4*o4+0]=fmaf(hv,v.x,acc[4*o4+0]); acc[4*o4+1]=fmaf(hv,v.y,acc[4*o4+1]);
                    acc[4*o4+2]=fmaf(hv,v.z,acc[4*o4+2]); acc[4*o4+3]=fmaf(hv,v.w,acc[4*o4+3]);
                }
            }
        }
    }
    float* op = out + ((n*32 + b)*32)*256 + t;
    #pragma unroll
    for (int o = 0; o < 32; o++)
        op[o*256] = 0.05f + 0.5f * tanhf((acc[o] - 0.3f) * 3.0f);
}

// ---------------- host threefry (derive subkeys) ----------------
static inline uint32_t rotl32(uint32_t x, int r) { return (x << r) | (x >> (32 - r)); }
static void tf_host(uint32_t k0, uint32_t k1, uint32_t c0, uint32_t c1,
                    uint32_t* o0, uint32_t* o1) {
    uint32_t ks[3] = { k0, k1, k0 ^ k1 ^ 0x1BD11BDAu };
    const int R[2][4] = { {13,15,26,6}, {17,29,16,24} };
    uint32_t x0 = c0 + k0, x1 = c1 + k1;
    for (int i = 0; i < 5; i++) {
        for (int j = 0; j < 4; j++) { x0 += x1; x1 = rotl32(x1, R[i & 1][j]); x1 ^= x0; }
        x0 += ks[(i + 1) % 3];
        x1 += ks[(i + 2) % 3] + (uint32_t)(i + 1);
    }
    *o0 = x0; *o1 = x1;
}

extern "C" void kernel_launch(void* const* d_in, const int* in_sizes, int n_in,
                              void* d_out, int out_size) {
    const float* x   = (const float*)d_in[0];
    const float* th1 = (const float*)d_in[1];
    const float* th2 = (const float*)d_in[2];
    const float* Rlf = (const float*)d_in[3];
    const float* Clf = (const float*)d_in[4];
    float* out = (float*)d_out;

    // key(42) = (0,42); split(key,4) -> k1..k4 (partitionable foldlike)
    uint2 kk[4];
    for (uint32_t i = 0; i < 4; i++) tf_host(0u, 42u, 0u, i, &kk[i].x, &kk[i].y);
    // bank subkeys: split(k2,4) = (kR,kC,kmu,k0); split(k3,4) likewise
    uint2 b1[4], b2[4];
    for (uint32_t i = 0; i < 4; i++) {
        tf_host(kk[1].x, kk[1].y, 0u, i, &b1[i].x, &b1[i].y);
        tf_host(kk[2].x, kk[2].y, 0u, i, &b2[i].x, &b2[i].y);
    }

    k_thn1 <<< (4352   + 255)/256, 256 >>> (kk[0], th1);
    k_thn2 <<< (135424 + 255)/256, 256 >>> (kk[3], th2);
    k_norm <<< 32, 256 >>> ();
    k_pmac1<<< 128, 256 >>> (x);
    k_beta <<< 2097152/256, 256 >>> (b1[0], b1[1], b1[2], b2[0], b2[1], b2[2], Rlf, Clf);
    k_s0   <<< 262144/256, 256 >>> (b1[3], b2[3]);
    k_scan <<< 128, 1024 >>> ();
    k_pmac2<<< dim3(32, 4), 256 >>> (out);
}

// round 5
// speedup vs baseline: 1.4723x; 1.4723x over previous
#include <cuda_runtime.h>
#include <stdint.h>

// ---------------- constants ----------------
#define EPSc   0.05f
#define DTc    0.1f
#define RMINc  1.0e5f
#define RMAXc  1.0e7f
#define CMINc  1.0e-7f
#define CMAXc  1.0e-4f

// ---------------- device scratch (static: no allocation allowed) ----------------
__device__ float g_thn1T[4*32*34];        // [n][o][m]
__device__ float g_thn2T[4*32*1058];      // [n][o][m]
__device__ float g_w1s  [4*33*32];        // [n][m][o]  (m=32 is bias)
__device__ float g_w2d  [4*1057*64];      // [n][j][2*o]  duplicated + K-permuted, j=1056 bias
__device__ float g_a1T  [4*32*256*32];    // [n][c][t][b]
__device__ float g_beta [2*256*1024*4];   // [bank][t][k][n]
__device__ float g_s0   [2*1024*4*32];    // [bank][k][n][b]
__device__ float g_yout [4*1024*256*32];  // [n][k][t][b]   (128 MB)

// ---------------- packed f32x2 FMA ----------------
#define FMA2(d, a, b, c) \
    asm("fma.rn.f32x2 %0, %1, %2, %3;" : "=l"(d) : "l"(a), "l"(b), "l"(c))

// ---------------- JAX threefry2x32 (partitionable semantics) ----------------
__device__ __forceinline__ uint2 tf2x32_d(uint32_t k0, uint32_t k1, uint32_t c0, uint32_t c1) {
    uint32_t ks2 = k0 ^ k1 ^ 0x1BD11BDAu;
    uint32_t x0 = c0 + k0, x1 = c1 + k1;
#define TFR(r) { x0 += x1; x1 = __funnelshift_l(x1, x1, (r)); x1 ^= x0; }
    TFR(13) TFR(15) TFR(26) TFR(6)   x0 += k1;  x1 += ks2 + 1u;
    TFR(17) TFR(29) TFR(16) TFR(24)  x0 += ks2; x1 += k0  + 2u;
    TFR(13) TFR(15) TFR(26) TFR(6)   x0 += k0;  x1 += k1  + 3u;
    TFR(17) TFR(29) TFR(16) TFR(24)  x0 += k1;  x1 += ks2 + 4u;
    TFR(13) TFR(15) TFR(26) TFR(6)   x0 += ks2; x1 += k0  + 5u;
#undef TFR
    return make_uint2(x0, x1);
}

__device__ __forceinline__ float u01p(uint2 key, uint32_t idx) {
    uint2 v = tf2x32_d(key.x, key.y, 0u, idx);
    uint32_t u = v.x ^ v.y;
    return __uint_as_float((u >> 9) | 0x3f800000u) - 1.0f;
}

// ---------------- kernel: noisy effective theta (pmac1) ----------------
__global__ void k_thn1(uint2 key, const float* __restrict__ th) {
    int i = blockIdx.x * blockDim.x + threadIdx.x;
    if (i >= 4*34*32) return;
    int o = i & 31; int nm = i >> 5; int m = nm % 34; int n = nm / 34;
    float u = u01p(key, (uint32_t)i);
    float noise = (u * 2.0f - 1.0f) * EPSc + 1.0f;
    float t = th[m*32 + o];
    t = fminf(fmaxf(t, -10.0f), 10.0f);
    if (fabsf(t) < 0.01f) t = 0.0f;
    g_thn1T[(n*32 + o)*34 + m] = t * noise;
}

// ---------------- kernel: noisy effective theta (pmac2) ----------------
__global__ void k_thn2(uint2 key, const float* __restrict__ th) {
    int i = blockIdx.x * blockDim.x + threadIdx.x;
    if (i >= 4*1058*32) return;
    int o = i & 31; int nm = i >> 5; int m = nm % 1058; int n = nm / 1058;
    float u = u01p(key, (uint32_t)i);
    float noise = (u * 2.0f - 1.0f) * EPSc + 1.0f;
    float t = th[m*32 + o];
    t = fminf(fmaxf(t, -10.0f), 10.0f);
    if (fabsf(t) < 0.01f) t = 0.0f;
    g_thn2T[(n*32 + o)*1058 + m] = t * noise;
}

// ---------------- kernel: normalize columns (one warp per (n,o)) ----------------
// pmac2 weights are written DUPLICATED (each o twice -> f32x2 operand) and
// K-PERMUTED: j = c*32+(g-1) for filter rows (g>=1), j = 1024+c for raw-a1 rows
// (g==0), j = 1056 for bias. This makes GEMM K-tiles contiguous in yout / a1T.
__global__ void k_norm() {
    int gid = blockIdx.x * blockDim.x + threadIdx.x;
    int w = gid >> 5, lane = gid & 31;
    if (w < 128) {          // pmac2 columns
        int n = w >> 5, o = w & 31;
        const float* col = &g_thn2T[(n*32 + o)*1058];
        float s = 0.0f;
        for (int m = lane; m < 1058; m += 32) s += fabsf(col[m]);
        #pragma unroll
        for (int d = 16; d > 0; d >>= 1) s += __shfl_xor_sync(0xffffffffu, s, d);
        float inv = 1.0f / (s + 1e-10f);
        for (int m = lane; m < 1057; m += 32) {
            int j;
            if (m == 1056) j = 1056;
            else {
                int c = m / 33, g = m % 33;
                j = (g == 0) ? (1024 + c) : (c*32 + g - 1);
            }
            float v = col[m] * inv;
            g_w2d[(n*1057 + j)*64 + 2*o    ] = v;
            g_w2d[(n*1057 + j)*64 + 2*o + 1] = v;
        }
    } else if (w < 256) {   // pmac1 columns
        int w2 = w - 128; int n = w2 >> 5, o = w2 & 31;
        const float* col = &g_thn1T[(n*32 + o)*34];
        float s = 0.0f;
        for (int m = lane; m < 34; m += 32) s += fabsf(col[m]);
        #pragma unroll
        for (int d = 16; d > 0; d >>= 1) s += __shfl_xor_sync(0xffffffffu, s, d);
        float inv = 1.0f / (s + 1e-10f);
        for (int m = lane; m < 33; m += 32) g_w1s[(n*33 + m)*32 + o] = col[m] * inv;
    }
}

// ---------------- kernel: pmac1 (x -> a1T, coalesced both sides) ----------------
// grid (32 t-chunks, 4 n), 256 threads = 8 t x 32 b
__global__ void __launch_bounds__(256) k_pmac1(const float* __restrict__ x) {
    int n = blockIdx.y;
    int tc = blockIdx.x;
    int tid = threadIdx.x;
    int tl = tid & 7, b = tid >> 3;
    int t = tc*8 + tl;
    __shared__ float w[33*32];
    __shared__ float osm[8][8][33];
    for (int i = tid; i < 33*32; i += 256) w[i] = g_w1s[n*33*32 + i];
    __syncthreads();
    const float* xp = x + ((size_t)(n*32 + b)*32)*256 + t;
    float acc[32];
    const float4* wb4 = (const float4*)&w[32*32];
    #pragma unroll
    for (int o4 = 0; o4 < 8; o4++) {
        float4 v = wb4[o4];
        acc[4*o4+0]=v.x; acc[4*o4+1]=v.y; acc[4*o4+2]=v.z; acc[4*o4+3]=v.w;
    }
    #pragma unroll 4
    for (int m = 0; m < 32; m++) {
        float xv = xp[(size_t)m*256];
        const float4* wr = (const float4*)&w[m*32];
        #pragma unroll
        for (int o4 = 0; o4 < 8; o4++) {
            float4 v = wr[o4];
            acc[4*o4+0]=fmaf(xv,v.x,acc[4*o4+0]); acc[4*o4+1]=fmaf(xv,v.y,acc[4*o4+1]);
            acc[4*o4+2]=fmaf(xv,v.z,acc[4*o4+2]); acc[4*o4+3]=fmaf(xv,v.w,acc[4*o4+3]);
        }
    }
    // activation + transposed (coalesced) store of a1T[n][o][t][b]
    for (int og = 0; og < 4; og++) {
        __syncthreads();
        #pragma unroll
        for (int oo = 0; oo < 8; oo++) {
            int o = og*8 + oo;
            osm[oo][tl][b] = 0.05f + 0.5f * tanhf((acc[o] - 0.3f) * 3.0f);
        }
        __syncthreads();
        int b_r = tid & 31, hi = tid >> 5;
        #pragma unroll
        for (int j = 0; j < 8; j++) {
            g_a1T[((size_t)(n*32 + og*8 + hi)*256 + tc*8 + j)*32 + b_r] = osm[hi][j][b_r];
        }
    }
}

// ---------------- kernel: beta for both banks ----------------
__global__ void k_beta(uint2 kR1, uint2 kC1, uint2 km1,
                       uint2 kR2, uint2 kC2, uint2 km2,
                       const float* __restrict__ Rlf, const float* __restrict__ Clf) {
    int i = blockIdx.x * blockDim.x + threadIdx.x;
    if (i >= 2*1048576) return;
    int bank = i >> 20;
    uint32_t e = (uint32_t)(i & 1048575);
    int k = (int)((e >> 2) & 1023u);
    uint2 kR = bank ? kR2 : kR1;
    uint2 kC = bank ? kC2 : kC1;
    uint2 km = bank ? km2 : km1;
    float nR = (u01p(kR, e) * 2.0f - 1.0f) * EPSc + 1.0f;
    float nC = (u01p(kC, e) * 2.0f - 1.0f) * EPSc + 1.0f;
    float mu =  u01p(km, e) * 0.2f + 1.0f;
    float Rr = Rlf[k*2 + bank], Cr = Clf[k*2 + bank];
    float Rt = (1.0f / (1.0f + expf(-Rr))) * (RMAXc - RMINc) + RMINc;
    float Ct = (1.0f / (1.0f + expf(-Cr))) * (CMAXc - CMINc) + CMINc;
    float RC = mu * (Rt * nR) * (Ct * nC);
    g_beta[i] = RC / (RC + DTc);
}

// ---------------- kernel: s0 for both banks ----------------
__global__ void k_s0(uint2 k01, uint2 k02) {
    int i = blockIdx.x * blockDim.x + threadIdx.x;
    if (i >= 262144) return;
    int bank = i >> 17;
    uint32_t e = (uint32_t)(i & 131071);
    g_s0[i] = u01p(bank ? k02 : k01, e);
}

// ---------------- kernel: fused two-bank scan ----------------
// grid 256 = (n 4, c 32, fh 2); 512 threads = 16 f x 32 b
__global__ void __launch_bounds__(512) k_scan() {
    int bi = blockIdx.x;
    int n = bi & 3, c = (bi >> 2) & 31, fh = bi >> 7;
    int f = fh*16 + (threadIdx.x >> 5), b = threadIdx.x & 31;
    int k = c*32 + f;
    float s = g_s0[(k*4 + n)*32 + b];
    float r = g_s0[131072 + (k*4 + n)*32 + b];
    const float* xp  = &g_a1T[((size_t)(n*32 + c)*256) * 32 + b];   // +t*32
    const float* b1p = &g_beta[(k*4 + n)];                          // +t*4096
    const float* b2p = b1p + 1048576;
    float* yp = &g_yout[((size_t)(n*1024 + k)*256) * 32 + b];       // +t*32
    #pragma unroll 4
    for (int t = 0; t < 256; t++) {
        float be1 = __ldg(b1p + (size_t)t*4096);
        float be2 = __ldg(b2p + (size_t)t*4096);
        float xv  = xp[t*32];
        yp[t*32] = r;                      // scan emits the PRE-update carry
        r = be2 * r + (1.0f - be2) * s;    // bank2 consumes y1[t] = current s
        s = be1 * s + (1.0f - be1) * xv;   // bank1 update
    }
}

// ---------------- kernel: pmac2 as register-tiled GEMM (f32x2) ----------------
// Per n: out[8192 m, 32 o] = h[8192, 1056] * W[1056, 32] + bias, m = t*32+b.
// Block: 256-row M tile, full N=32. Thread: 8 rows x 4 cols via 16 FFMA2/k.
// K order permuted (yout rows 0..1023, then a1 rows 1024..1055) - weights match.
__global__ void __launch_bounds__(256) k_pmac2(float* __restrict__ out) {
    const int n  = blockIdx.y;
    const int M0 = blockIdx.x * 256;
    const int tid = threadIdx.x;
    const int cg = tid & 7;        // col group: o = cg*4 + c
    const int rg = tid >> 3;       // row group: m = M0 + rg*8 + rr
    __shared__ float hs[2][16][256];
    __shared__ float wd[2][16][64];
    const float* ybase = g_yout + (size_t)n*1024*8192 + M0;   // + j*8192
    const float* abase = g_a1T  + (size_t)n*32*8192   + M0;   // + (j-1024)*8192
    const float* wbase = g_w2d  + (size_t)n*1057*64;          // + j*64

    unsigned long long acc[4][4];
    {
        const unsigned long long* bp =
            (const unsigned long long*)(wbase + 1056*64 + cg*8);
        #pragma unroll
        for (int cc = 0; cc < 4; cc++) {
            unsigned long long bv = bp[cc];
            #pragma unroll
            for (int rp = 0; rp < 4; rp++) acc[rp][cc] = bv;
        }
    }

    auto load_stage = [&](int s, int buf) {
        int k0 = s * 16;
        #pragma unroll
        for (int j = 0; j < 4; j++) {
            int ch = tid + 256*j;
            int kk = ch >> 6, f4 = ch & 63;
            int jg = k0 + kk;
            const float* src = (jg < 1024)
                ? (ybase + (size_t)jg*8192 + f4*4)
                : (abase + (size_t)(jg - 1024)*8192 + f4*4);
            unsigned dst = (unsigned)__cvta_generic_to_shared(&hs[buf][kk][f4*4]);
            asm volatile("cp.async.cg.shared.global [%0], [%1], 16;" :: "r"(dst), "l"(src));
        }
        {
            int kk = tid >> 4, f4 = tid & 15;
            const float* src = wbase + (size_t)(k0 + kk)*64 + f4*4;
            unsigned dst = (unsigned)__cvta_generic_to_shared(&wd[buf][kk][f4*4]);
            asm volatile("cp.async.cg.shared.global [%0], [%1], 16;" :: "r"(dst), "l"(src));
        }
        asm volatile("cp.async.commit_group;");
    };

    load_stage(0, 0);
    for (int s = 0; s < 66; s++) {
        int buf = s & 1;
        if (s < 65) { load_stage(s + 1, buf ^ 1); asm volatile("cp.async.wait_group 1;"); }
        else        { asm volatile("cp.async.wait_group 0;"); }
        __syncthreads();
        #pragma unroll
        for (int kk = 0; kk < 16; kk++) {
            ulonglong2 hA = *(const ulonglong2*)(&hs[buf][kk][rg*8]);
            ulonglong2 hB = *(const ulonglong2*)(&hs[buf][kk][rg*8 + 4]);
            ulonglong2 wA = *(const ulonglong2*)(&wd[buf][kk][cg*8]);
            ulonglong2 wB = *(const ulonglong2*)(&wd[buf][kk][cg*8 + 4]);
            unsigned long long h[4] = { hA.x, hA.y, hB.x, hB.y };
            unsigned long long wv[4] = { wA.x, wA.y, wB.x, wB.y };
            #pragma unroll
            for (int rp = 0; rp < 4; rp++) {
                #pragma unroll
                for (int cc = 0; cc < 4; cc++)
                    FMA2(acc[rp][cc], h[rp], wv[cc], acc[rp][cc]);
            }
        }
        __syncthreads();
    }

    // epilogue: activation + store (out[n][b][o][t])
    #pragma unroll
    for (int rp = 0; rp < 4; rp++) {
        int m0 = M0 + rg*8 + rp*2;            // even; m0 and m0+1 share t
        int t = m0 >> 5, b = m0 & 31;
        float* op0 = out + ((size_t)(n*32 + b)*32)*256 + t;
        #pragma unroll
        for (int cc = 0; cc < 4; cc++) {
            int o = cg*4 + cc;
            float lo = __uint_as_float((unsigned)(acc[rp][cc] & 0xffffffffu));
            float hi = __uint_as_float((unsigned)(acc[rp][cc] >> 32));
            lo = 0.05f + 0.5f * tanhf((lo - 0.3f) * 3.0f);
            hi = 0.05f + 0.5f * tanhf((hi - 0.3f) * 3.0f);
            op0[(size_t)o*256]        = lo;     // row m0   (b)
            op0[8192 + (size_t)o*256] = hi;     // row m0+1 (b+1)
        }
    }
}

// ---------------- host threefry (derive subkeys) ----------------
static inline uint32_t rotl32(uint32_t x, int r) { return (x << r) | (x >> (32 - r)); }
static void tf_host(uint32_t k0, uint32_t k1, uint32_t c0, uint32_t c1,
                    uint32_t* o0, uint32_t* o1) {
    uint32_t ks[3] = { k0, k1, k0 ^ k1 ^ 0x1BD11BDAu };
    const int R[2][4] = { {13,15,26,6}, {17,29,16,24} };
    uint32_t x0 = c0 + k0, x1 = c1 + k1;
    for (int i = 0; i < 5; i++) {
        for (int j = 0; j < 4; j++) { x0 += x1; x1 = rotl32(x1, R[i & 1][j]); x1 ^= x0; }
        x0 += ks[(i + 1) % 3];
        x1 += ks[(i + 2) % 3] + (uint32_t)(i + 1);
    }
    *o0 = x0; *o1 = x1;
}

extern "C" void kernel_launch(void* const* d_in, const int* in_sizes, int n_in,
                              void* d_out, int out_size) {
    const float* x   = (const float*)d_in[0];
    const float* th1 = (const float*)d_in[1];
    const float* th2 = (const float*)d_in[2];
    const float* Rlf = (const float*)d_in[3];
    const float* Clf = (const float*)d_in[4];
    float* out = (float*)d_out;

    // key(42) = (0,42); split(key,4) -> k1..k4 (partitionable)
    uint2 kk[4];
    for (uint32_t i = 0; i < 4; i++) tf_host(0u, 42u, 0u, i, &kk[i].x, &kk[i].y);
    uint2 b1[4], b2[4];
    for (uint32_t i = 0; i < 4; i++) {
        tf_host(kk[1].x, kk[1].y, 0u, i, &b1[i].x, &b1[i].y);
        tf_host(kk[2].x, kk[2].y, 0u, i, &b2[i].x, &b2[i].y);
    }

    k_thn1 <<< (4352   + 255)/256, 256 >>> (kk[0], th1);
    k_thn2 <<< (135424 + 255)/256, 256 >>> (kk[3], th2);
    k_norm <<< 32, 256 >>> ();
    k_pmac1<<< dim3(32, 4), 256 >>> (x);
    k_beta <<< 2097152/256, 256 >>> (b1[0], b1[1], b1[2], b2[0], b2[1], b2[2], Rlf, Clf);
    k_s0   <<< 262144/256, 256 >>> (b1[3], b2[3]);
    k_scan <<< 256, 512 >>> ();
    k_pmac2<<< dim3(32, 4), 256 >>> (out);
}